// round 5
// baseline (speedup 1.0000x reference)
#include <cuda_runtime.h>
#include <math.h>

#define DIM   1024
#define VOCAB 50257
#define G     148
#define NROW  7        // rows per block: 148*7 = 1036 >= 1024

__device__ float g_yk[DIM];
__device__ float g_z[DIM];
__device__ float g_bm[G];        // per-block max
__device__ float g_bs[G];        // per-block sum of exp(z - m_b)
__device__ unsigned int g_bar;   // zero-init; reset by finishing block

// ---------------- K1: distributed gather of filters[:,0] ----------------
__global__ void yk_kernel(const float* __restrict__ filters) {
    int j = blockIdx.x * 32 + threadIdx.x;   // 32 x 32 = 1024
    float v = filters[(size_t)j * VOCAB];
    g_yk[j] = (j == DIM - 1) ? v : fmaxf(v, 0.0f);
}

// ---------------- K2: matvec + gate + last-block softmax ----------------
__global__ void __launch_bounds__(512, 1)
main_kernel(const float* __restrict__ w_t,
            const float* __restrict__ w_h,
            float* __restrict__ out)
{
    const int tid  = threadIdx.x;
    const int bid  = blockIdx.x;
    const int warp = tid >> 5, lane = tid & 31;

    __shared__ float s_y[DIM];
    __shared__ float part[14];
    __shared__ float zloc[NROW];
    __shared__ int   s_last;
    __shared__ float sred[16];

    // warp w < 14: row i = w>>1 (0..6), matrix = w&1 (0=w_t, 1=w_h).
    const int i   = warp >> 1;
    const int mat = warp & 1;
    const int row = bid * NROW + i;
    const bool active = (warp < 14) && (row < DIM);

    // Weight loads issued BEFORE the grid sync (overlap K1 via PDL).
    float4 wv[8];
    if (active) {
        const float* W = mat ? w_h : w_t;
        const float4* Wrow = (const float4*)(W + (size_t)row * DIM);
        #pragma unroll
        for (int k = 0; k < 8; k++)
            wv[k] = Wrow[k * 32 + lane];
    }

    cudaGridDependencySynchronize();   // K1's writes visible

    if (tid < 256)
        ((float4*)s_y)[tid] = ((const float4*)g_yk)[tid];
    __syncthreads();

    if (active) {
        const float4* y4 = (const float4*)s_y;
        float a0 = 0.0f, a1 = 0.0f;
        #pragma unroll
        for (int k = 0; k < 8; k += 2) {
            float4 y0 = y4[k * 32 + lane];
            float4 y1 = y4[(k + 1) * 32 + lane];
            a0 += wv[k].x * y0.x + wv[k].y * y0.y + wv[k].z * y0.z + wv[k].w * y0.w;
            a1 += wv[k+1].x * y1.x + wv[k+1].y * y1.y + wv[k+1].z * y1.z + wv[k+1].w * y1.w;
        }
        float acc = a0 + a1;
        #pragma unroll
        for (int o = 16; o; o >>= 1) acc += __shfl_xor_sync(0xffffffffu, acc, o);
        if (lane == 0) part[warp] = acc;
    }
    __syncthreads();

    if (tid < NROW) {
        int r = bid * NROW + tid;
        float zr = -1e30f;
        if (r < DIM) {
            float T = part[2 * tid];
            float H = part[2 * tid + 1];
            float t = 1.0f / (1.0f + __expf(-T));
            float g = fmaxf(H, 0.0f);
            zr = t * g + (1.0f - t) * s_y[r];
            __stcg(&g_z[r], zr);
        }
        zloc[tid] = zr;
    }
    __syncthreads();

    // Thread 0: per-block (max, exp-sum) over <=7 z's; release; arrive.
    if (tid == 0) {
        float m = -1e30f;
        #pragma unroll
        for (int k = 0; k < NROW; k++) m = fmaxf(m, zloc[k]);
        float s = 0.0f;
        if (m > -1e29f) {
            #pragma unroll
            for (int k = 0; k < NROW; k++)
                if (zloc[k] > -1e29f) s += __expf(zloc[k] - m);
        }
        __stcg(&g_bm[bid], m);
        __stcg(&g_bs[bid], s);
        __threadfence();                       // release z, bm, bs
        unsigned int old = atomicAdd(&g_bar, 1u);
        s_last = (old == G - 1u);
    }
    __syncthreads();
    if (!s_last) return;

    // -------- This block observed all arrivals: do the softmax tail --------
    __threadfence();                           // acquire

    // Global max over 148 per-block maxes (one element per thread).
    float mm = (tid < G) ? __ldcg(&g_bm[tid]) : -1e30f;
    float m = mm;
    #pragma unroll
    for (int o = 16; o; o >>= 1) m = fmaxf(m, __shfl_xor_sync(0xffffffffu, m, o));
    if (lane == 0) sred[warp] = m;
    __syncthreads();
    if (warp == 0) {
        float v = (lane < 16) ? sred[lane] : -1e30f;
        #pragma unroll
        for (int o = 8; o; o >>= 1) v = fmaxf(v, __shfl_xor_sync(0xffffffffu, v, o));
        if (lane == 0) sred[0] = v;
    }
    __syncthreads();
    const float M = sred[0];
    __syncthreads();

    // Global sum: s_b * exp(m_b - M).
    float s = (tid < G) ? __ldcg(&g_bs[tid]) * __expf(mm - M) : 0.0f;
    #pragma unroll
    for (int o = 16; o; o >>= 1) s += __shfl_xor_sync(0xffffffffu, s, o);
    if (lane == 0) sred[warp] = s;
    __syncthreads();
    if (warp == 0) {
        float v = (lane < 16) ? sred[lane] : 0.0f;
        #pragma unroll
        for (int o = 8; o; o >>= 1) v += __shfl_xor_sync(0xffffffffu, v, o);
        if (lane == 0) sred[0] = v;
    }
    __syncthreads();

    const float lse = M + __logf(sred[0]);
    out[tid]       = __ldcg(&g_z[tid])       - lse;
    out[tid + 512] = __ldcg(&g_z[tid + 512]) - lse;

    __syncthreads();
    if (tid == 0) g_bar = 0u;   // reset for next graph replay
}

extern "C" void kernel_launch(void* const* d_in, const int* in_sizes, int n_in,
                              void* d_out, int out_size) {
    // metadata order: input (int32, unused), filters, w_t, w_h
    const float* filters = (const float*)d_in[1];
    const float* w_t     = (const float*)d_in[2];
    const float* w_h     = (const float*)d_in[3];
    float* out           = (float*)d_out;

    yk_kernel<<<32, 32>>>(filters);

    cudaLaunchConfig_t cfg = {};
    cfg.gridDim  = dim3(G, 1, 1);
    cfg.blockDim = dim3(512, 1, 1);
    cfg.dynamicSmemBytes = 0;
    cfg.stream = 0;
    cudaLaunchAttribute attrs[1];
    attrs[0].id = cudaLaunchAttributeProgrammaticStreamSerialization;
    attrs[0].val.programmaticStreamSerializationAllowed = 1;
    cfg.attrs = attrs;
    cfg.numAttrs = 1;
    cudaLaunchKernelEx(&cfg, main_kernel, w_t, w_h, out);
}

// round 6
// speedup vs baseline: 1.2435x; 1.2435x over previous
#include <cuda_runtime.h>
#include <math.h>

#define DIM   1024
#define VOCAB 50257
#define G     148
#define NROW  7        // rows per block: 148*7 = 1036 >= 1024

__device__ float g_z[DIM];
__device__ unsigned int g_bar;   // zero-init; reset by finishing block

__global__ void __launch_bounds__(512, 1)
fused_kernel(const float* __restrict__ filters,
             const float* __restrict__ w_t,
             const float* __restrict__ w_h,
             float* __restrict__ out)
{
    const int tid  = threadIdx.x;
    const int bid  = blockIdx.x;
    const int warp = tid >> 5, lane = tid & 31;

    __shared__ float s_y[DIM];
    __shared__ float part[14];
    __shared__ int   s_last;
    __shared__ float sred[16];

    // warp w < 14: row i = w>>1 (0..6), matrix = w&1 (0=w_t, 1=w_h).
    const int i   = warp >> 1;
    const int mat = warp & 1;
    const int row = bid * NROW + i;
    const bool active = (warp < 14) && (row < DIM);

    // --- Gather loads FIRST (they gate the __syncthreads below) ---
    float gv0 = filters[(size_t)tid * VOCAB];
    float gv1 = filters[(size_t)(tid + 512) * VOCAB];

    // --- Weight loads second (consumed per-warp after the sync) ---
    float4 wv[8];
    if (active) {
        const float* W = mat ? w_h : w_t;
        const float4* Wrow = (const float4*)(W + (size_t)row * DIM);
        #pragma unroll
        for (int k = 0; k < 8; k++)
            wv[k] = Wrow[k * 32 + lane];
    }

    // Stage y into shared (relu; last element passes through).
    s_y[tid]       = fmaxf(gv0, 0.0f);
    s_y[tid + 512] = (tid + 512 == DIM - 1) ? gv1 : fmaxf(gv1, 0.0f);
    __syncthreads();

    if (active) {
        const float4* y4 = (const float4*)s_y;
        float a0 = 0.0f, a1 = 0.0f;
        #pragma unroll
        for (int k = 0; k < 8; k += 2) {
            float4 y0 = y4[k * 32 + lane];
            float4 y1 = y4[(k + 1) * 32 + lane];
            a0 += wv[k].x * y0.x + wv[k].y * y0.y + wv[k].z * y0.z + wv[k].w * y0.w;
            a1 += wv[k+1].x * y1.x + wv[k+1].y * y1.y + wv[k+1].z * y1.z + wv[k+1].w * y1.w;
        }
        float acc = a0 + a1;
        #pragma unroll
        for (int o = 16; o; o >>= 1) acc += __shfl_xor_sync(0xffffffffu, acc, o);
        if (lane == 0) part[warp] = acc;
    }
    __syncthreads();

    if (tid < NROW) {
        int r = bid * NROW + tid;
        if (r < DIM) {
            float T = part[2 * tid];
            float H = part[2 * tid + 1];
            float t = 1.0f / (1.0f + __expf(-T));
            float g = fmaxf(H, 0.0f);
            __stcg(&g_z[r], t * g + (1.0f - t) * s_y[r]);
        }
    }
    __syncthreads();   // orders the z stores before tid0's fence (CTA scope)

    // threadFenceReduction pattern: release + arrive; closer block finishes.
    if (tid == 0) {
        __threadfence();                        // release z stores (GPU scope)
        unsigned int old = atomicAdd(&g_bar, 1u);
        s_last = (old == G - 1u);
    }
    __syncthreads();
    if (!s_last) return;

    // -------- Finishing block: all z visible; do log-softmax --------
    __threadfence();                            // acquire

    float z0 = __ldcg(&g_z[tid]);
    float z1 = __ldcg(&g_z[tid + 512]);

    float m = fmaxf(z0, z1);
    #pragma unroll
    for (int o = 16; o; o >>= 1) m = fmaxf(m, __shfl_xor_sync(0xffffffffu, m, o));
    if (lane == 0) sred[warp] = m;
    __syncthreads();
    if (warp == 0) {
        float v = (lane < 16) ? sred[lane] : -1e30f;
        #pragma unroll
        for (int o = 8; o; o >>= 1) v = fmaxf(v, __shfl_xor_sync(0xffffffffu, v, o));
        if (lane == 0) sred[0] = v;
    }
    __syncthreads();
    const float gmax = sred[0];
    __syncthreads();

    float s = __expf(z0 - gmax) + __expf(z1 - gmax);
    #pragma unroll
    for (int o = 16; o; o >>= 1) s += __shfl_xor_sync(0xffffffffu, s, o);
    if (lane == 0) sred[warp] = s;
    __syncthreads();
    if (warp == 0) {
        float v = (lane < 16) ? sred[lane] : 0.0f;
        #pragma unroll
        for (int o = 8; o; o >>= 1) v += __shfl_xor_sync(0xffffffffu, v, o);
        if (lane == 0) sred[0] = v;
    }
    __syncthreads();

    const float lse = gmax + __logf(sred[0]);
    out[tid]       = z0 - lse;
    out[tid + 512] = z1 - lse;

    __syncthreads();
    if (tid == 0) g_bar = 0u;   // reset for next graph replay
}

extern "C" void kernel_launch(void* const* d_in, const int* in_sizes, int n_in,
                              void* d_out, int out_size) {
    // metadata order: input (int32, unused), filters, w_t, w_h
    const float* filters = (const float*)d_in[1];
    const float* w_t     = (const float*)d_in[2];
    const float* w_h     = (const float*)d_in[3];
    float* out           = (float*)d_out;

    fused_kernel<<<G, 512>>>(filters, w_t, w_h, out);
}